// round 8
// baseline (speedup 1.0000x reference)
#include <cuda_runtime.h>

#define BAG 15
#define IM 28
#define PS 8
#define POSMAX (IM - PS) /* 20 */
#define LAM 0.001f
#define TPB 128
#define MAXB 65536
#define MAXBLK 512
#define NPMAX 225

__device__ __align__(16) float g_WiT[66 * 16];   // WiT[k*16+u] = Wi[u*66+k], col 15 = 0
__device__ __align__(16) float g_reffT[BAG * 16]; // g_reffT[j*16+u] = Reff[u][j], col 15 = 0
__device__ float g_state[BAG * MAXB];             // [u][b]
__device__ unsigned int g_pos[MAXB];              // r | (c<<8)
__device__ float g_partial[NPMAX * MAXBLK];       // [pair][block]
__device__ int g_pidx[NPMAX];                     // flattened idx = i*15+j of active mask entries
__device__ int g_pi[NPMAX];
__device__ int g_pj[NPMAX];
__device__ int g_np;

__device__ __forceinline__ float warp_sum(float v) {
    v += __shfl_xor_sync(0xffffffffu, v, 16);
    v += __shfl_xor_sync(0xffffffffu, v, 8);
    v += __shfl_xor_sync(0xffffffffu, v, 4);
    v += __shfl_xor_sync(0xffffffffu, v, 2);
    v += __shfl_xor_sync(0xffffffffu, v, 1);
    return v;
}

// acc[0..14] += val * base[0..14]   (base 16B-aligned, padded to 16 floats)
#define FMA15(val, base) do {                                              \
    const float4* _wp = (const float4*)(base);                             \
    float4 _w0 = _wp[0], _w1 = _wp[1], _w2 = _wp[2], _w3 = _wp[3];         \
    float _v = (val);                                                      \
    acc[0]  = fmaf(_v, _w0.x, acc[0]);  acc[1]  = fmaf(_v, _w0.y, acc[1]); \
    acc[2]  = fmaf(_v, _w0.z, acc[2]);  acc[3]  = fmaf(_v, _w0.w, acc[3]); \
    acc[4]  = fmaf(_v, _w1.x, acc[4]);  acc[5]  = fmaf(_v, _w1.y, acc[5]); \
    acc[6]  = fmaf(_v, _w1.z, acc[6]);  acc[7]  = fmaf(_v, _w1.w, acc[7]); \
    acc[8]  = fmaf(_v, _w2.x, acc[8]);  acc[9]  = fmaf(_v, _w2.y, acc[9]); \
    acc[10] = fmaf(_v, _w2.z, acc[10]); acc[11] = fmaf(_v, _w2.w, acc[11]);\
    acc[12] = fmaf(_v, _w3.x, acc[12]); acc[13] = fmaf(_v, _w3.y, acc[13]);\
    acc[14] = fmaf(_v, _w3.z, acc[14]);                                    \
} while (0)

__global__ void prep_kernel(const float* __restrict__ Wi, const float* __restrict__ mask) {
    int t = threadIdx.x;
    for (int idx = t; idx < 66 * 16; idx += 256) {
        int k = idx >> 4, u = idx & 15;
        g_WiT[idx] = (u < 15) ? Wi[u * 66 + k] : 0.0f;
    }
    if (t == 0) {
        int np = 0;
        for (int idx = 0; idx < 225; idx++) {
            if (mask[idx] != 0.0f) {
                g_pidx[np] = idx;
                g_pi[np] = idx / 15;
                g_pj[np] = idx % 15;
                np++;
            }
        }
        g_np = np;
    }
}

// MODE 0: first step (no recurrent, emit coact). 1: middle (recurrent + coact).
// 2: last (recurrent + logits, no coact / no pos update).
template <int MODE>
__global__ __launch_bounds__(TPB, 4) void step_kernel(
    const float* __restrict__ x,
    const float* __restrict__ bi, const float* __restrict__ gamma,
    const float* __restrict__ beta, const float* __restrict__ rb,
    const float* __restrict__ Wc, const float* __restrict__ bc,
    const float* __restrict__ Wo, const float* __restrict__ bo,
    float* __restrict__ out, int B)
{
    __shared__ float sh_s[BAG][TPB];
    __shared__ float sh_w[NPMAX][4];

    int tid = threadIdx.x;
    int b = blockIdx.x * TPB + tid;
    int bb = (b < B) ? b : 0;
    bool on = (b < B);

    int r, c;
    if (MODE == 0) { r = 10; c = 10; }
    else { unsigned int p = g_pos[bb]; r = (int)(p & 255u); c = (int)(p >> 8); }

    float acc[15];
#pragma unroll
    for (int u = 0; u < 15; u++) acc[u] = bi[u] + (MODE ? rb[u] : 0.0f);

    if (MODE) {
        float so;
#pragma unroll
        for (int j = 0; j < 15; j++) {
            so = g_state[j * MAXB + bb];
            FMA15(so, g_reffT + j * 16);
        }
        float pr = (float)r * (2.0f / (float)POSMAX) - 1.0f;
        float pc = (float)c * (2.0f / (float)POSMAX) - 1.0f;
        FMA15(pr, g_WiT + 64 * 16);
        FMA15(pc, g_WiT + 65 * 16);
    }

    // ---- 8x8 patch: per row 2-3 aligned float4 + 2-stage select shift ----
    {
        const float* img = x + (size_t)bb * (IM * IM);
        int sh = c & 3;
        int cb = c & ~3;
        bool s2 = (sh & 2) != 0;
        bool s1 = (sh & 1) != 0;
        bool need2 = (sh != 0);
#pragma unroll
        for (int i = 0; i < 8; i++) {
            const float4* rp = (const float4*)(img + (r + i) * IM + cb);
            float4 a0 = rp[0];
            float4 a1 = rp[1];
            float4 a2 = need2 ? rp[2] : make_float4(0.f, 0.f, 0.f, 0.f);
            float v0 = a0.x, v1 = a0.y, v2 = a0.z, v3 = a0.w;
            float v4 = a1.x, v5 = a1.y, v6 = a1.z, v7 = a1.w;
            float v8 = a2.x, v9 = a2.y, v10 = a2.z;
            float t0 = s2 ? v2 : v0, t1 = s2 ? v3 : v1, t2 = s2 ? v4 : v2;
            float t3 = s2 ? v5 : v3, t4 = s2 ? v6 : v4, t5 = s2 ? v7 : v5;
            float t6 = s2 ? v8 : v6, t7 = s2 ? v9 : v7, t8 = s2 ? v10 : v8;
            float f0 = s1 ? t1 : t0, f1 = s1 ? t2 : t1, f2 = s1 ? t3 : t2;
            float f3 = s1 ? t4 : t3, f4 = s1 ? t5 : t4, f5 = s1 ? t6 : t5;
            float f6 = s1 ? t7 : t6, f7 = s1 ? t8 : t7;
            FMA15(f0, g_WiT + (i * 8 + 0) * 16);
            FMA15(f1, g_WiT + (i * 8 + 1) * 16);
            FMA15(f2, g_WiT + (i * 8 + 2) * 16);
            FMA15(f3, g_WiT + (i * 8 + 3) * 16);
            FMA15(f4, g_WiT + (i * 8 + 4) * 16);
            FMA15(f5, g_WiT + (i * 8 + 5) * 16);
            FMA15(f6, g_WiT + (i * 8 + 6) * 16);
            FMA15(f7, g_WiT + (i * 8 + 7) * 16);
        }
    }

    // ---- relu + layernorm ----
    float mu = 0.0f;
#pragma unroll
    for (int u = 0; u < 15; u++) { acc[u] = fmaxf(acc[u], 0.0f); mu += acc[u]; }
    mu *= (1.0f / 15.0f);
    float var = 0.0f;
#pragma unroll
    for (int u = 0; u < 15; u++) { float d = acc[u] - mu; acc[u] = d; var += d * d; }
    var *= (1.0f / 15.0f);
    float inv = rsqrtf(var + 1e-5f);
    float s[15];
#pragma unroll
    for (int u = 0; u < 15; u++) s[u] = acc[u] * inv * gamma[u] + beta[u];

    if (MODE < 2) {
        if (on) {
#pragma unroll
            for (int u = 0; u < 15; u++) g_state[u * MAXB + b] = s[u];
        }
        // control head (tanh skipped: monotone odd, decisions identical)
        float c0 = bc[0], c1 = bc[1];
#pragma unroll
        for (int u = 0; u < 15; u++) {
            c0 = fmaf(s[u], Wc[u], c0);
            c1 = fmaf(s[u], Wc[15 + u], c1);
        }
        bool rsel = fabsf(c0) >= fabsf(c1);
        int mr = rsel ? ((c0 > 0.0f) ? 1 : ((c0 < 0.0f) ? -1 : 0)) : 0;
        int mc = rsel ? 0 : ((c1 > 0.0f) ? 1 : ((c1 < 0.0f) ? -1 : 0));
        int nr = min(max(r + mr, 0), POSMAX);
        int nc = min(max(c + mc, 0), POSMAX);
        if (on) g_pos[b] = (unsigned int)nr | ((unsigned int)nc << 8);

        // coact partials over active pairs only (deterministic order)
#pragma unroll
        for (int u = 0; u < 15; u++) sh_s[u][tid] = on ? s[u] : 0.0f;
        __syncthreads();
        int np = g_np;
        int wid = tid >> 5, lane = tid & 31;
        for (int p = 0; p < np; p++) {
            float v = sh_s[g_pi[p]][tid] * sh_s[g_pj[p]][tid];
            v = warp_sum(v);
            if (lane == 0) sh_w[p][wid] = v;
        }
        __syncthreads();
        for (int p = tid; p < np; p += TPB)
            g_partial[p * MAXBLK + blockIdx.x] =
                (sh_w[p][0] + sh_w[p][1]) + (sh_w[p][2] + sh_w[p][3]);
    } else {
        if (on) {
#pragma unroll
            for (int o = 0; o < 10; o++) {
                float l = bo[o];
#pragma unroll
                for (int u = 0; u < 15; u++) l = fmaf(s[u], Wo[o * 15 + u], l);
                out[(size_t)b * 10 + o] = l;
            }
        }
    }
}

__global__ void reff_kernel(const float* __restrict__ R, const float* __restrict__ mask,
                            int B, int nblk) {
    int tid = threadIdx.x;
    // zero masked-out entries + padding column (disjoint from active writes below)
    for (int idx = tid; idx < 240; idx += 256) {
        if (idx < 225) {
            int i = idx / 15, j = idx % 15;
            if (mask[idx] == 0.0f) g_reffT[j * 16 + i] = 0.0f;
        } else {
            g_reffT[(idx - 225) * 16 + 15] = 0.0f;
        }
    }
    int np = g_np;
    int wid = tid >> 5, lane = tid & 31;
    for (int p = wid; p < np; p += 8) {
        float a = 0.0f;
        for (int t = lane; t < nblk; t += 32) a += g_partial[p * MAXBLK + t];
        a = warp_sum(a);
        if (lane == 0) {
            int idx = g_pidx[p];
            int i = idx / 15, j = idx % 15;
            float val = (R[idx] - LAM * (a / (float)B)) * mask[idx];
            g_reffT[j * 16 + i] = val;
        }
    }
}

extern "C" void kernel_launch(void* const* d_in, const int* in_sizes, int n_in,
                              void* d_out, int out_size) {
    const float* x     = (const float*)d_in[0];
    const float* Wi    = (const float*)d_in[1];
    const float* bi    = (const float*)d_in[2];
    const float* gamma = (const float*)d_in[3];
    const float* beta  = (const float*)d_in[4];
    const float* R     = (const float*)d_in[5];
    const float* rb    = (const float*)d_in[6];
    const float* mask  = (const float*)d_in[7];
    const float* Wc    = (const float*)d_in[8];
    const float* bc    = (const float*)d_in[9];
    const float* Wo    = (const float*)d_in[10];
    const float* bo    = (const float*)d_in[11];
    float* out = (float*)d_out;

    int B = in_sizes[0] / (IM * IM);
    if (B > MAXB) B = MAXB;
    int nblk = (B + TPB - 1) / TPB;

    prep_kernel<<<1, 256>>>(Wi, mask);
    step_kernel<0><<<nblk, TPB>>>(x, bi, gamma, beta, rb, Wc, bc, Wo, bo, out, B);
    reff_kernel<<<1, 256>>>(R, mask, B, nblk);
    step_kernel<1><<<nblk, TPB>>>(x, bi, gamma, beta, rb, Wc, bc, Wo, bo, out, B);
    reff_kernel<<<1, 256>>>(R, mask, B, nblk);
    step_kernel<1><<<nblk, TPB>>>(x, bi, gamma, beta, rb, Wc, bc, Wo, bo, out, B);
    reff_kernel<<<1, 256>>>(R, mask, B, nblk);
    step_kernel<1><<<nblk, TPB>>>(x, bi, gamma, beta, rb, Wc, bc, Wo, bo, out, B);
    reff_kernel<<<1, 256>>>(R, mask, B, nblk);
    step_kernel<2><<<nblk, TPB>>>(x, bi, gamma, beta, rb, Wc, bc, Wo, bo, out, B);
}